// round 4
// baseline (speedup 1.0000x reference)
#include <cuda_runtime.h>
#include <cuda_bf16.h>
#include <cstdint>

// ---------------- problem constants ----------------
#define BSZ 2
#define SEQ 2048
#define HID 2048
#define HD  256
#define NH  8
#define SCALING 0.0625f
#define NEG_INF (-1000000000.0f)

#define KP_BIG  6144   // 3*2048
#define KP_ATT  768    // 3*256

// ---------------- scratch (device globals) ----------------
__device__ float          g_Qproj[(long)BSZ*SEQ*NH*HD];
__device__ float          g_K    [(long)BSZ*SEQ*HD];
__device__ float          g_V    [(long)BSZ*SEQ*HD];
__device__ float          g_AO   [(long)BSZ*SEQ*NH*HD];
__device__ __nv_bfloat16  g_hs3 [(long)BSZ*SEQ*KP_BIG];        // A rows: [hi|hi|lo]
__device__ __nv_bfloat16  g_Wq3 [(long)HID*KP_BIG];            // B rows (N x K): [hi|lo|hi]
__device__ __nv_bfloat16  g_Wk3 [(long)HD*KP_BIG];
__device__ __nv_bfloat16  g_Wv3 [(long)HD*KP_BIG];
__device__ __nv_bfloat16  g_Wo3 [(long)HID*KP_BIG];
__device__ __nv_bfloat16  g_Q3  [(long)BSZ*NH*SEQ*KP_ATT];
__device__ __nv_bfloat16  g_K3  [(long)BSZ*SEQ*KP_ATT];
__device__ __nv_bfloat16  g_V3T [(long)BSZ*HD*KP_BIG];
__device__ __nv_bfloat16  g_P3  [(long)BSZ*NH*SEQ*KP_BIG];
__device__ __nv_bfloat16  g_AO3 [(long)BSZ*SEQ*KP_BIG];

// ---------------- low-level helpers ----------------
__device__ __forceinline__ uint32_t smem_u32(const void* p) {
    uint32_t a;
    asm("{ .reg .u64 t; cvta.to.shared.u64 t, %1; cvt.u32.u64 %0, t; }" : "=r"(a) : "l"(p));
    return a;
}
__device__ __forceinline__ void cp_async16(uint32_t dst, const void* src) {
    asm volatile("cp.async.cg.shared.global [%0], [%1], 16;" :: "r"(dst), "l"(src));
}
__device__ __forceinline__ void cp_commit() { asm volatile("cp.async.commit_group;"); }
template<int N> __device__ __forceinline__ void cp_wait() {
    asm volatile("cp.async.wait_group %0;" :: "n"(N));
}
__device__ __forceinline__ void ldmatrix_x4(uint32_t* r, uint32_t addr) {
    asm volatile("ldmatrix.sync.aligned.m8n8.x4.shared.b16 {%0,%1,%2,%3}, [%4];"
        : "=r"(r[0]), "=r"(r[1]), "=r"(r[2]), "=r"(r[3]) : "r"(addr));
}
__device__ __forceinline__ void mma16816(float* d, const uint32_t* a, const uint32_t* b) {
    asm volatile("mma.sync.aligned.m16n8k16.row.col.f32.bf16.bf16.f32 "
        "{%0,%1,%2,%3}, {%4,%5,%6,%7}, {%8,%9}, {%0,%1,%2,%3};"
        : "+f"(d[0]), "+f"(d[1]), "+f"(d[2]), "+f"(d[3])
        : "r"(a[0]), "r"(a[1]), "r"(a[2]), "r"(a[3]), "r"(b[0]), "r"(b[1]));
}

// ---------------- HMMA bf16x3 GEMM ----------------
// C(MxN fp32) = alpha * A(M x Kp) * B(N x Kp)^T (+ causal)
// tile 128x128, BK=64 (128B rows, XOR-8 swizzle), cp.async double buffer
// grid (N/128, M/128, Z); b = z/nh, h = z%nh
#define SM_BUFSZ 32768                 // A 16K + B 16K
#define SMEM_DYN (2*SM_BUFSZ)

// copy 128 rows x 64 halves (128B/row) with swizzle
__device__ __forceinline__ void cpasync_tile(uint32_t sdst, const __nv_bfloat16* g,
                                             int ld, int k0, int tid) {
    #pragma unroll
    for (int i = 0; i < 4; i++) {
        int idx = tid + i * 256;          // 0..1023
        int row = idx >> 3;
        int chunk = idx & 7;
        uint32_t dst = sdst + row * 128 + ((chunk ^ (row & 7)) << 4);
        cp_async16(dst, g + (long)row * ld + k0 + chunk * 8);
    }
}

__global__ __launch_bounds__(256)
void gemm_bf16x3(const __nv_bfloat16* __restrict__ A, const __nv_bfloat16* __restrict__ B,
                 float* __restrict__ C,
                 int Kp, int lda, int ldb, int ldc,
                 long sAz, long sBb, long sCb, long sCh, int nh,
                 float alpha, int causal)
{
    extern __shared__ char smem[];
    const int tid  = threadIdx.x;
    const int wid  = tid >> 5;
    const int lane = tid & 31;
    const int z = blockIdx.z, b = z / nh, h = z - b * nh;
    const int rowT = blockIdx.y, colT = blockIdx.x;

    C += (long)b * sCb + (long)h * sCh;

    if (causal && colT > rowT) {
        float* cp = C + (long)(rowT * 128) * ldc + colT * 128;
        float4 v = make_float4(NEG_INF, NEG_INF, NEG_INF, NEG_INF);
        for (int i = tid; i < 128 * 32; i += 256) {
            int r = i >> 5, s4 = i & 31;
            *reinterpret_cast<float4*>(cp + (long)r * ldc + s4 * 4) = v;
        }
        return;
    }

    const uint32_t sb = smem_u32(smem);
    A += (long)z * sAz + (long)(rowT * 128) * lda;
    B += (long)b * sBb + (long)(colT * 128) * ldb;

    const int wm = wid >> 1;      // 0..3  (M)
    const int wn = wid & 1;       // 0..1  (N)

    // ldmatrix lane addressing
    const int a_r  = lane & 15;          // row within 16
    const int a_c8 = (lane >> 4) << 3;   // 0 or 8 (halves)
    const int b_n  = (((lane >> 4) & 1) << 3) + (lane & 7);
    const int b_k8 = ((lane >> 3) & 1) << 3;

    float acc[2][8][4];
    #pragma unroll
    for (int mi = 0; mi < 2; mi++)
        #pragma unroll
        for (int ni = 0; ni < 8; ni++)
            #pragma unroll
            for (int e = 0; e < 4; e++) acc[mi][ni][e] = 0.0f;

    const int nk = Kp >> 6;
    // prologue: chunk 0 -> buffer 0
    cpasync_tile(sb,         A, lda, 0, tid);
    cpasync_tile(sb + 16384, B, ldb, 0, tid);
    cp_commit();

    for (int i = 0; i < nk; i++) {
        const int buf = i & 1;
        if (i + 1 < nk) {
            const int nb = buf ^ 1;
            cpasync_tile(sb + nb * SM_BUFSZ,         A, lda, (i + 1) << 6, tid);
            cpasync_tile(sb + nb * SM_BUFSZ + 16384, B, ldb, (i + 1) << 6, tid);
            cp_commit();
            cp_wait<1>();
        } else {
            cp_wait<0>();
        }
        __syncthreads();

        const uint32_t sA = sb + buf * SM_BUFSZ;
        const uint32_t sBs = sA + 16384;

        #pragma unroll
        for (int ks = 0; ks < 4; ks++) {
            const int kb = ks << 4;  // k16 base within 64
            uint32_t afr[2][4];
            #pragma unroll
            for (int mi = 0; mi < 2; mi++) {
                const int r = wm * 32 + mi * 16 + a_r;
                const int c = kb + a_c8;            // multiple of 8
                uint32_t addr = sA + r * 128 + ((((c >> 3) ^ (r & 7))) << 4);
                ldmatrix_x4(afr[mi], addr);
            }
            uint32_t bfr[4][4];                     // 4 calls x (2 n8-tiles each)
            #pragma unroll
            for (int nj = 0; nj < 4; nj++) {
                const int n = wn * 64 + nj * 16 + b_n;
                const int c = kb + b_k8;
                uint32_t addr = sBs + n * 128 + ((((c >> 3) ^ (n & 7))) << 4);
                ldmatrix_x4(bfr[nj], addr);       // B stored [n][k]: plain (non-trans)
            }
            #pragma unroll
            for (int mi = 0; mi < 2; mi++)
                #pragma unroll
                for (int nj = 0; nj < 4; nj++) {
                    mma16816(acc[mi][nj * 2 + 0], afr[mi], &bfr[nj][0]);
                    mma16816(acc[mi][nj * 2 + 1], afr[mi], &bfr[nj][2]);
                }
        }
        __syncthreads();
    }

    // epilogue
    const int tr = lane >> 2;        // 0..7
    const int tc = (lane & 3) * 2;   // 0,2,4,6
    const bool diag = (causal && colT == rowT);
    #pragma unroll
    for (int mi = 0; mi < 2; mi++) {
        #pragma unroll
        for (int ni = 0; ni < 8; ni++) {
            const int col = colT * 128 + wn * 64 + ni * 8 + tc;
            #pragma unroll
            for (int half = 0; half < 2; half++) {
                const int row = rowT * 128 + wm * 32 + mi * 16 + half * 8 + tr;
                float2 v;
                v.x = acc[mi][ni][half * 2 + 0] * alpha;
                v.y = acc[mi][ni][half * 2 + 1] * alpha;
                if (diag) {
                    if (col + 0 > row) v.x += NEG_INF;
                    if (col + 1 > row) v.y += NEG_INF;
                }
                *reinterpret_cast<float2*>(C + (long)row * ldc + col) = v;
            }
        }
    }
}

// ---------------- converters ----------------
__device__ __forceinline__ void split_bf16(float x, __nv_bfloat16& hi, __nv_bfloat16& lo) {
    hi = __float2bfloat16(x);
    lo = __float2bfloat16(x - __bfloat162float(hi));
}

// fp32 (M x 2048) -> bf16 (M x 6144) rows [hi|hi|lo]
__global__ void convertA(const float* __restrict__ in, __nv_bfloat16* __restrict__ out) {
    long idx = (long)blockIdx.x * 256 + threadIdx.x;
    long r = idx >> 11; int c = (int)(idx & 2047);
    __nv_bfloat16 hi, lo; split_bf16(in[idx], hi, lo);
    long rb = r * (long)KP_BIG;
    out[rb + c] = hi; out[rb + 2048 + c] = hi; out[rb + 4096 + c] = lo;
}

// fp32 (K x N) -> bf16 (N x 3K) rows [hi|lo|hi]  (transpose)
__global__ void convertBT(const float* __restrict__ in, __nv_bfloat16* __restrict__ out,
                          int K, int N, long sIn, long sOut) {
    __shared__ float t[32][33];
    in  += (long)blockIdx.z * sIn;
    out += (long)blockIdx.z * sOut;
    const int tx = threadIdx.x, ty = threadIdx.y;
    const int k = blockIdx.y * 32 + ty;
    const int n = blockIdx.x * 32 + tx;
    t[ty][tx] = in[(long)k * N + n];
    __syncthreads();
    const int n2 = blockIdx.x * 32 + ty;
    const int k2 = blockIdx.y * 32 + tx;
    __nv_bfloat16 hi, lo; split_bf16(t[tx][ty], hi, lo);
    long rb = (long)n2 * 3 * K;
    out[rb + k2] = hi; out[rb + K + k2] = lo; out[rb + 2 * K + k2] = hi;
}

// RoPE Q + transpose + split -> rows [hi|hi|lo]
__global__ void rope_q3(const float* __restrict__ Qp, const float* __restrict__ cosb,
                        const float* __restrict__ sinb, __nv_bfloat16* __restrict__ Q3) {
    long idx = (long)blockIdx.x * 256 + threadIdx.x;
    const int dh = (int)(idx & 127);
    long t = idx >> 7;
    const int h = (int)(t & 7); t >>= 3;
    const int s = (int)(t & 2047);
    const int b = (int)(t >> 11);

    const float* src = Qp + ((long)(b * SEQ + s) * (NH * HD) + h * HD);
    const float x1 = src[dh], x2 = src[dh + 128];
    const long cs = (long)(b * SEQ + s) * HD;
    const float c1 = cosb[cs + dh],       s1 = sinb[cs + dh];
    const float c2 = cosb[cs + dh + 128], s2 = sinb[cs + dh + 128];
    const float q1 = x1 * c1 - x2 * s1;
    const float q2 = x2 * c2 + x1 * s2;

    __nv_bfloat16 h1, l1, h2, l2;
    split_bf16(q1, h1, l1); split_bf16(q2, h2, l2);
    __nv_bfloat16* dst = Q3 + ((long)(b * NH + h) * SEQ + s) * KP_ATT;
    dst[dh] = h1;       dst[256 + dh] = h1;       dst[512 + dh] = l1;
    dst[dh + 128] = h2; dst[256 + dh + 128] = h2; dst[512 + dh + 128] = l2;
}

// RoPE K + split -> rows [hi|lo|hi]
__global__ void rope_k3(const float* __restrict__ Kp, const float* __restrict__ cosb,
                        const float* __restrict__ sinb, __nv_bfloat16* __restrict__ K3) {
    long idx = (long)blockIdx.x * 256 + threadIdx.x;
    const int dh = (int)(idx & 127);
    long t = idx >> 7;
    const int s = (int)(t & 2047);
    const int b = (int)(t >> 11);

    const float* src = Kp + (long)(b * SEQ + s) * HD;
    const float x1 = src[dh], x2 = src[dh + 128];
    const long cs = (long)(b * SEQ + s) * HD;
    const float c1 = cosb[cs + dh],       s1 = sinb[cs + dh];
    const float c2 = cosb[cs + dh + 128], s2 = sinb[cs + dh + 128];
    const float k1 = x1 * c1 - x2 * s1;
    const float k2 = x2 * c2 + x1 * s2;

    __nv_bfloat16 h1, l1, h2, l2;
    split_bf16(k1, h1, l1); split_bf16(k2, h2, l2);
    __nv_bfloat16* dst = K3 + ((long)b * SEQ + s) * KP_ATT;
    dst[dh] = h1;       dst[256 + dh] = l1;       dst[512 + dh] = h1;
    dst[dh + 128] = h2; dst[256 + dh + 128] = l2; dst[512 + dh + 128] = h2;
}

// softmax rows (len 2048) in place + split into P3 rows [hi|hi|lo]
__global__ __launch_bounds__(256)
void softmax_p3(float* __restrict__ W, __nv_bfloat16* __restrict__ P3) {
    const long row = blockIdx.x;
    float* p = W + row * (long)SEQ;
    __nv_bfloat16* p3 = P3 + row * (long)KP_BIG;
    const int tid = threadIdx.x;
    __shared__ float red[256];

    float v[8];
    #pragma unroll
    for (int j = 0; j < 8; j++) v[j] = p[tid + j * 256];

    float m = v[0];
    #pragma unroll
    for (int j = 1; j < 8; j++) m = fmaxf(m, v[j]);
    red[tid] = m; __syncthreads();
    for (int s = 128; s > 0; s >>= 1) { if (tid < s) red[tid] = fmaxf(red[tid], red[tid + s]); __syncthreads(); }
    m = red[0]; __syncthreads();

    float sum = 0.0f;
    #pragma unroll
    for (int j = 0; j < 8; j++) { v[j] = __expf(v[j] - m); sum += v[j]; }
    red[tid] = sum; __syncthreads();
    for (int s = 128; s > 0; s >>= 1) { if (tid < s) red[tid] += red[tid + s]; __syncthreads(); }
    const float inv = 1.0f / red[0]; __syncthreads();

    #pragma unroll
    for (int j = 0; j < 8; j++) {
        const int c = tid + j * 256;
        const float pv = v[j] * inv;
        p[c] = pv;
        __nv_bfloat16 hi, lo; split_bf16(pv, hi, lo);
        p3[c] = hi; p3[2048 + c] = hi; p3[4096 + c] = lo;
    }
}

// ---------------- launch ----------------
extern "C" void kernel_launch(void* const* d_in, const int* in_sizes, int n_in,
                              void* d_out, int out_size)
{
    const float* hs   = (const float*)d_in[0];
    const float* cosb = (const float*)d_in[1];
    const float* sinb = (const float*)d_in[2];
    const float* Wq   = (const float*)d_in[4];
    const float* Wk   = (const float*)d_in[5];
    const float* Wv   = (const float*)d_in[6];
    const float* Wo   = (const float*)d_in[7];

    float* out_attn = (float*)d_out;
    float* out_w    = (float*)d_out + (long)BSZ * SEQ * HID;

    cudaFuncSetAttribute(gemm_bf16x3, cudaFuncAttributeMaxDynamicSharedMemorySize, SMEM_DYN);

    const long SS  = (long)SEQ * SEQ;
    const long SD3 = (long)SEQ * KP_ATT;

    // conversions
    convertBT<<<dim3(64, 64, 1), dim3(32, 32)>>>(Wq, g_Wq3, HID, HID, 0, 0);
    convertBT<<<dim3(8,  64, 1), dim3(32, 32)>>>(Wk, g_Wk3, HID, HD, 0, 0);
    convertBT<<<dim3(8,  64, 1), dim3(32, 32)>>>(Wv, g_Wv3, HID, HD, 0, 0);
    convertBT<<<dim3(64, 64, 1), dim3(32, 32)>>>(Wo, g_Wo3, HID, HID, 0, 0);
    convertA <<<32768, 256>>>(hs, g_hs3);

    // projections
    gemm_bf16x3<<<dim3(16, 32, 1), 256, SMEM_DYN>>>(g_hs3, g_Wq3, g_Qproj,
        KP_BIG, KP_BIG, KP_BIG, HID, 0, 0, 0, 0, 1, 1.0f, 0);
    gemm_bf16x3<<<dim3(2, 32, 1), 256, SMEM_DYN>>>(g_hs3, g_Wk3, g_K,
        KP_BIG, KP_BIG, KP_BIG, HD, 0, 0, 0, 0, 1, 1.0f, 0);
    gemm_bf16x3<<<dim3(2, 32, 1), 256, SMEM_DYN>>>(g_hs3, g_Wv3, g_V,
        KP_BIG, KP_BIG, KP_BIG, HD, 0, 0, 0, 0, 1, 1.0f, 0);

    // rope + split
    rope_q3<<<16384, 256>>>(g_Qproj, cosb, sinb, g_Q3);
    rope_k3<<<2048, 256>>>(g_K, cosb, sinb, g_K3);

    // V transpose-split (per batch)
    convertBT<<<dim3(8, 64, 2), dim3(32, 32)>>>(g_V, g_V3T, SEQ, HD,
        (long)SEQ * HD, (long)HD * KP_BIG);

    // logits = scale * Q K^T + causal
    gemm_bf16x3<<<dim3(16, 16, 16), 256, SMEM_DYN>>>(g_Q3, g_K3, out_w,
        KP_ATT, KP_ATT, KP_ATT, SEQ,
        SD3, SD3, (long)NH * SS, SS, NH, SCALING, 1);

    // softmax + P split
    softmax_p3<<<32768, 256>>>(out_w, g_P3);

    // attn_out = P V (per b,h)
    gemm_bf16x3<<<dim3(2, 16, 16), 256, SMEM_DYN>>>(g_P3, g_V3T, g_AO,
        KP_BIG, KP_BIG, KP_BIG, NH * HD,
        (long)SEQ * KP_BIG, (long)HD * KP_BIG,
        (long)SEQ * NH * HD, (long)HD, NH, 1.0f, 0);

    // output projection
    convertA<<<32768, 256>>>(g_AO, g_AO3);
    gemm_bf16x3<<<dim3(16, 32, 1), 256, SMEM_DYN>>>(g_AO3, g_Wo3, out_attn,
        KP_BIG, KP_BIG, KP_BIG, HID, 0, 0, 0, 0, 1, 1.0f, 0);
}

// round 5
// speedup vs baseline: 7.5273x; 7.5273x over previous
#include <cuda_runtime.h>
#include <cuda_bf16.h>
#include <cstdint>

typedef unsigned long long ull;

// ---------------- problem constants ----------------
#define BSZ 2
#define SEQ 2048
#define HID 2048
#define HD  256
#define NH  8
#define SCALING 0.0625f

// ---------------- scratch (device globals) ----------------
__device__ float g_Qp [(long)BSZ*SEQ*NH*HD];   // pre-RoPE Q (b,s,h,d)
__device__ float g_Q  [(long)BSZ*NH*SEQ*HD];   // RoPE'd, scaled Q (b,h,s,d)
__device__ float g_KV [(long)BSZ*SEQ*512];     // [token][0:256]=K, [256:512]=V
__device__ float g_Kt [(long)BSZ*HD*SEQ];      // K^T per batch (d, s2)
__device__ float g_AO [(long)BSZ*SEQ*NH*HD];   // attn out (b,s,h*d)
__device__ float g_Wkv[(long)HID*512];         // [Wk | Wv]

// ---------------- f32x2 helpers ----------------
__device__ __forceinline__ ull pk2(float x) {
    ull r; unsigned u = __float_as_uint(x);
    asm("mov.b64 %0, {%1, %1};" : "=l"(r) : "r"(u));
    return r;
}
__device__ __forceinline__ ull fma2(ull a, ull b, ull c) {
    ull d;
    asm("fma.rn.f32x2 %0, %1, %2, %3;" : "=l"(d) : "l"(a), "l"(b), "l"(c));
    return d;
}
__device__ __forceinline__ float2 unpk2(ull v) {
    unsigned lo, hi;
    asm("mov.b64 {%0, %1}, %2;" : "=r"(lo), "=r"(hi) : "l"(v));
    return make_float2(__uint_as_float(lo), __uint_as_float(hi));
}

// ---------------- fp32 GEMM, 128x128 tile, BK=16, f32x2 math ----------------
// C = A(M x K) * B(K x N)   A row-major(lda), B row-major(ldb), C row-major(ldc)
// batched: A += z*sAz ; B += b*sBb ; C += b*sCb + h*sCh, b=z/nh, h=z%nh
// causalQK: skip tiles with colT > rowT entirely (no fill)
// causalPV: truncate K at (rowT+1)*128
#define BK 16

__global__ __launch_bounds__(256)
void sgemm2(const float* __restrict__ A, const float* __restrict__ B,
            float* __restrict__ C,
            int K, int lda, int ldb, int ldc,
            long sAz, long sBb, long sCb, long sCh, int nh,
            int causalQK, int causalPV)
{
    __shared__ float As[2][BK][128];
    __shared__ float Bs[2][BK][128];

    const int tid = threadIdx.x;
    const int z = blockIdx.z, b = z / nh, h = z - b * nh;
    const int rowT = blockIdx.y, colT = blockIdx.x;
    if (causalQK && colT > rowT) return;

    A += (long)z * sAz + (long)(rowT * 128) * lda;
    B += (long)b * sBb + colT * 128;
    C += (long)b * sCb + (long)h * sCh;

    const int Keff = causalPV ? min(K, (rowT + 1) * 128) : K;
    const int nk = Keff >> 4;

    const int tr = tid >> 4;       // 0..15
    const int tc = tid & 15;       // 0..15

    // prefetch indices
    const int af0 = tid, af1 = tid + 256;          // A float4 ids
    const int am0 = af0 >> 2, ak0 = (af0 & 3) << 2;
    const int am1 = af1 >> 2, ak1 = (af1 & 3) << 2;
    const int bk0 = af0 >> 5, bn0 = (af0 & 31) << 2;
    const int bk1 = af1 >> 5, bn1 = (af1 & 31) << 2;

    float4 pa0, pa1, pb0, pb1;
    // stage 0 loads
    pa0 = *(const float4*)(A + (long)am0 * lda + ak0);
    pa1 = *(const float4*)(A + (long)am1 * lda + ak1);
    pb0 = *(const float4*)(B + (long)bk0 * ldb + bn0);
    pb1 = *(const float4*)(B + (long)bk1 * ldb + bn1);
    // store stage 0 (A transposed)
    As[0][ak0 + 0][am0] = pa0.x; As[0][ak0 + 1][am0] = pa0.y;
    As[0][ak0 + 2][am0] = pa0.z; As[0][ak0 + 3][am0] = pa0.w;
    As[0][ak1 + 0][am1] = pa1.x; As[0][ak1 + 1][am1] = pa1.y;
    As[0][ak1 + 2][am1] = pa1.z; As[0][ak1 + 3][am1] = pa1.w;
    *(float4*)&Bs[0][bk0][bn0] = pb0;
    *(float4*)&Bs[0][bk1][bn1] = pb1;
    __syncthreads();

    ull acc[8][4];
    #pragma unroll
    for (int m = 0; m < 8; m++)
        #pragma unroll
        for (int n = 0; n < 4; n++) acc[m][n] = 0ull;

    for (int s = 0; s < nk; s++) {
        const int buf = s & 1;
        if (s + 1 < nk) {
            const float* A1 = A + (s + 1) * BK;
            const float* B1 = B + (long)(s + 1) * BK * ldb;
            pa0 = *(const float4*)(A1 + (long)am0 * lda + ak0);
            pa1 = *(const float4*)(A1 + (long)am1 * lda + ak1);
            pb0 = *(const float4*)(B1 + (long)bk0 * ldb + bn0);
            pb1 = *(const float4*)(B1 + (long)bk1 * ldb + bn1);
        }
        #pragma unroll
        for (int k = 0; k < BK; k++) {
            float4 a0 = *(const float4*)&As[buf][k][tr * 4];
            float4 a1 = *(const float4*)&As[buf][k][64 + tr * 4];
            ulonglong2 bv0 = *(const ulonglong2*)&Bs[buf][k][tc * 4];
            ulonglong2 bv1 = *(const ulonglong2*)&Bs[buf][k][64 + tc * 4];
            ull bn_[4] = { bv0.x, bv0.y, bv1.x, bv1.y };
            ull am_[8] = { pk2(a0.x), pk2(a0.y), pk2(a0.z), pk2(a0.w),
                           pk2(a1.x), pk2(a1.y), pk2(a1.z), pk2(a1.w) };
            #pragma unroll
            for (int m = 0; m < 8; m++)
                #pragma unroll
                for (int n = 0; n < 4; n++)
                    acc[m][n] = fma2(am_[m], bn_[n], acc[m][n]);
        }
        if (s + 1 < nk) {
            __syncthreads();
            const int nb = buf ^ 1;
            As[nb][ak0 + 0][am0] = pa0.x; As[nb][ak0 + 1][am0] = pa0.y;
            As[nb][ak0 + 2][am0] = pa0.z; As[nb][ak0 + 3][am0] = pa0.w;
            As[nb][ak1 + 0][am1] = pa1.x; As[nb][ak1 + 1][am1] = pa1.y;
            As[nb][ak1 + 2][am1] = pa1.z; As[nb][ak1 + 3][am1] = pa1.w;
            *(float4*)&Bs[nb][bk0][bn0] = pb0;
            *(float4*)&Bs[nb][bk1][bn1] = pb1;
            __syncthreads();
        }
    }

    // epilogue
    #pragma unroll
    for (int m = 0; m < 8; m++) {
        const int r = rowT * 128 + ((m < 4) ? (tr * 4 + m) : (64 + tr * 4 + m - 4));
        float* cp = C + (long)r * ldc + colT * 128;
        #pragma unroll
        for (int n = 0; n < 4; n++) {
            const int c = (n < 2) ? (tc * 4 + 2 * n) : (64 + tc * 4 + 2 * (n - 2));
            float2 v = unpk2(acc[m][n]);
            *(float2*)(cp + c) = v;
        }
    }
}

// ---------------- weight concat [Wk | Wv] ----------------
__global__ void concat_wkv(const float* __restrict__ Wk, const float* __restrict__ Wv,
                           float* __restrict__ Wkv) {
    int idx = blockIdx.x * 256 + threadIdx.x;      // HID*512
    int k = idx >> 9, n = idx & 511;
    Wkv[idx] = (n < 256) ? Wk[k * 256 + n] : Wv[k * 256 + (n - 256)];
}

// ---------------- RoPE Q: transpose (b,s,h,d)->(b,h,s,d), scale ----------------
__global__ void rope_q(const float* __restrict__ Qp, const float* __restrict__ cosb,
                       const float* __restrict__ sinb, float* __restrict__ Qt) {
    long idx = (long)blockIdx.x * 256 + threadIdx.x;   // B*S*NH*128
    const int dh = (int)(idx & 127);
    long t = idx >> 7;
    const int h = (int)(t & 7); t >>= 3;
    const int s = (int)(t & 2047);
    const int b = (int)(t >> 11);

    const float* src = Qp + ((long)(b * SEQ + s) * (NH * HD) + h * HD);
    const float x1 = src[dh], x2 = src[dh + 128];
    const long cs = (long)(b * SEQ + s) * HD;
    const float c1 = cosb[cs + dh],       s1 = sinb[cs + dh];
    const float c2 = cosb[cs + dh + 128], s2 = sinb[cs + dh + 128];

    float* dst = Qt + (((long)(b * NH + h) * SEQ + s) * HD);
    dst[dh]       = (x1 * c1 - x2 * s1) * SCALING;
    dst[dh + 128] = (x2 * c2 + x1 * s2) * SCALING;
}

// ---------------- RoPE K from g_KV, write K^T (b, d, s2) ----------------
__global__ void rope_kT(const float* __restrict__ KV, const float* __restrict__ cosb,
                        const float* __restrict__ sinb, float* __restrict__ Kt) {
    long idx = (long)blockIdx.x * 256 + threadIdx.x;   // B*128*2048, s2 fastest
    const int s2 = (int)(idx & 2047);
    const int dh = (int)((idx >> 11) & 127);
    const int b  = (int)(idx >> 18);

    const float* src = KV + (long)(b * SEQ + s2) * 512;
    const float x1 = src[dh], x2 = src[dh + 128];
    const long cs = (long)(b * SEQ + s2) * HD;
    const float c1 = cosb[cs + dh],       s1 = sinb[cs + dh];
    const float c2 = cosb[cs + dh + 128], s2v = sinb[cs + dh + 128];

    Kt[((long)(b * HD + dh)) * SEQ + s2]       = x1 * c1 - x2 * s1;
    Kt[((long)(b * HD + dh + 128)) * SEQ + s2] = x2 * c2 + x1 * s2v;
}

// ---------------- causal softmax: row r uses only first r+1 logits ------------
__global__ __launch_bounds__(256)
void softmax_causal(float* __restrict__ W) {
    const long row = blockIdx.x;                 // (b,h,s1) flat
    const int r = (int)(row & 2047);
    const int len = r + 1;
    float* p = W + row * (long)SEQ;
    const int tid = threadIdx.x;
    __shared__ float red[256];

    float v[8];
    float m = -3.0e38f;
    #pragma unroll
    for (int j = 0; j < 8; j++) {
        const int c = tid + j * 256;
        v[j] = (c < len) ? p[c] : -3.0e38f;
        m = fmaxf(m, v[j]);
    }
    red[tid] = m; __syncthreads();
    for (int s = 128; s > 0; s >>= 1) {
        if (tid < s) red[tid] = fmaxf(red[tid], red[tid + s]);
        __syncthreads();
    }
    m = red[0]; __syncthreads();

    float sum = 0.0f;
    #pragma unroll
    for (int j = 0; j < 8; j++) {
        const int c = tid + j * 256;
        v[j] = (c < len) ? __expf(v[j] - m) : 0.0f;
        sum += v[j];
    }
    red[tid] = sum; __syncthreads();
    for (int s = 128; s > 0; s >>= 1) {
        if (tid < s) red[tid] += red[tid + s];
        __syncthreads();
    }
    const float inv = 1.0f / red[0]; __syncthreads();

    #pragma unroll
    for (int j = 0; j < 8; j++) {
        const int c = tid + j * 256;
        p[c] = v[j] * inv;          // exact 0 above diagonal
    }
}

// ---------------- launch ----------------
extern "C" void kernel_launch(void* const* d_in, const int* in_sizes, int n_in,
                              void* d_out, int out_size)
{
    const float* hs   = (const float*)d_in[0];
    const float* cosb = (const float*)d_in[1];
    const float* sinb = (const float*)d_in[2];
    const float* Wq   = (const float*)d_in[4];
    const float* Wk   = (const float*)d_in[5];
    const float* Wv   = (const float*)d_in[6];
    const float* Wo   = (const float*)d_in[7];

    float* out_attn = (float*)d_out;                          // (B,S,H)
    float* out_w    = (float*)d_out + (long)BSZ * SEQ * HID;  // (B,NH,S,S)

    const long SS = (long)SEQ * SEQ;

    // 0) concat K/V weights
    concat_wkv<<<(HID * 512) / 256, 256>>>(Wk, Wv, g_Wkv);

    // 1) Q projection: (4096 x 2048) @ (2048 x 2048)
    sgemm2<<<dim3(16, 32, 1), 256>>>(hs, Wq, g_Qp,
        HID, HID, HID, HID, 0, 0, 0, 0, 1, 0, 0);

    // 2) KV projection: (4096 x 2048) @ (2048 x 512)
    sgemm2<<<dim3(4, 32, 1), 256>>>(hs, g_Wkv, g_KV,
        HID, HID, 512, 512, 0, 0, 0, 0, 1, 0, 0);

    // 3) RoPE Q (+transpose+scale), RoPE K (+transpose)
    rope_q <<<16384, 256>>>(g_Qp, cosb, sinb, g_Q);
    rope_kT<<<2048, 256>>>(g_KV, cosb, sinb, g_Kt);

    // 4) logits = Q K^T (scaled via Q), causal tile skip
    sgemm2<<<dim3(16, 16, 16), 256>>>(g_Q, g_Kt, out_w,
        HD, HD, SEQ, SEQ,
        (long)SEQ * HD, (long)HD * SEQ, (long)NH * SS, SS, NH, 1, 0);

    // 5) causal softmax (writes exact zeros above diagonal)
    softmax_causal<<<32768, 256>>>(out_w);

    // 6) attn = P @ V, K-loop truncated by causality
    sgemm2<<<dim3(2, 16, 16), 256>>>(out_w, g_KV + 256, g_AO,
        SEQ, SEQ, 512, HID,
        SS, (long)SEQ * 512, (long)SEQ * HID, (long)HD, NH, 0, 1);

    // 7) output projection: (4096 x 2048) @ (2048 x 2048)
    sgemm2<<<dim3(16, 32, 1), 256>>>(g_AO, Wo, out_attn,
        HID, HID, HID, HID, 0, 0, 0, 0, 1, 0, 0);
}